// round 16
// baseline (speedup 1.0000x reference)
#include <cuda_runtime.h>
#include <math.h>

#define NCH   64
#define NLEN  2048
#define LW    128
#define KK    1921
#define DCOMP 4

#define MK    52     // Krylov dimension
#define APG   132    // fp32 G smem pitch (16B-aligned rows, conflict-free f4)
#define APQT  132    // transposed Q pitch
#define NR    12     // refined subspace size
#define APR   13     // U16/W16 pitch (doubles)

__device__ double g_G[NCH * LW * LW];       // fp64 Gram matrices
__device__ float  g_V4[NCH * LW * DCOMP];   // top-4 eigenvectors, interleaved

// single-barrier 128-thread reduction (caller alternates buffers)
__device__ __forceinline__ float bsum128(float v, volatile float* r4) {
#pragma unroll
    for (int o = 16; o; o >>= 1) v += __shfl_xor_sync(0xffffffffu, v, o);
    if ((threadIdx.x & 31) == 0) r4[threadIdx.x >> 5] = v;
    __syncthreads();
    return (r4[0] + r4[1]) + (r4[2] + r4[3]);
}
// joint dual reduction, single barrier
__device__ __forceinline__ float2 bsum128x2(float a, float b, volatile float* r8) {
#pragma unroll
    for (int o = 16; o; o >>= 1) {
        a += __shfl_xor_sync(0xffffffffu, a, o);
        b += __shfl_xor_sync(0xffffffffu, b, o);
    }
    if ((threadIdx.x & 31) == 0) {
        r8[threadIdx.x >> 5] = a;
        r8[4 + (threadIdx.x >> 5)] = b;
    }
    __syncthreads();
    return make_float2((r8[0] + r8[1]) + (r8[2] + r8[3]),
                       (r8[4] + r8[5]) + (r8[6] + r8[7]));
}

// ---------------------------------------------------------------------------
// Fused per-channel solver. 128 threads per CTA, one CTA per channel.
// ---------------------------------------------------------------------------
__global__ void __launch_bounds__(128, 1) eigen_kernel(const float* __restrict__ x) {
    extern __shared__ char smraw[];
    float*  G32 = (float*)smraw;                 // 128*132 f32
    float*  Qt  = G32 + LW * APG;                // 52*132  f32 (row j = q_j)
    double* U16 = (double*)(Qt + MK * APQT);     // 128*13  f64
    double* W16 = U16 + LW * APR;                // 128*13  f64
    float*  xs  = (float*)W16;                   // overlay (gram stage only)

    __shared__ double cd[LW];
    __shared__ __align__(16) float u[LW];
    __shared__ float  cvec[MK];
    __shared__ float  rA[8], rB[4];
    __shared__ double dred[4][NR];
    __shared__ double salpha[MK];
    __shared__ double sbeta[MK];
    __shared__ float  sa32[MK];
    __shared__ float  sbf[MK];
    __shared__ float  sb232[MK];
    __shared__ float  Ytr32[NR][MK];
    __shared__ float  cpw32[NR][MK];
    __shared__ float  lam32[NR];
    __shared__ double H16[NR * APR];
    __shared__ double Z16[NR * APR];
    __shared__ int    sp[6], sq[6];
    __shared__ double dc6[6], ds6[6];
    __shared__ int    idx4[4];

    int tid = threadIdx.x;
    int lane = tid & 31, wid = tid >> 5;
    int bc = blockIdx.x;
    double* Gd = g_G + (size_t)bc * LW * LW;

    // ================= Gram stage =================
    {
        const float* xp = x + bc * NLEN;
        for (int i = tid; i < NLEN; i += 128) xs[i] = xp[i];
        __syncthreads();

        // first row: fp32 products (f4 broadcast side), fp64 accumulation / 32
        // FULL chunks cover exactly [0, 1888); tail covers [1888, 1921).
        int m = tid;
        double dacc = 0.0;
        for (int chunk = 0; chunk < 1888; chunk += 32) {
            float f0 = 0, f1 = 0, f2 = 0, f3 = 0;
#pragma unroll
            for (int k = 0; k < 32; k += 4) {
                float4 xk = *(const float4*)&xs[chunk + k];
                f0 = fmaf(xk.x, xs[chunk + k + m],     f0);
                f1 = fmaf(xk.y, xs[chunk + k + 1 + m], f1);
                f2 = fmaf(xk.z, xs[chunk + k + 2 + m], f2);
                f3 = fmaf(xk.w, xs[chunk + k + 3 + m], f3);
            }
            dacc += (double)((f0 + f1) + (f2 + f3));
        }
        {   // tail chunk [1888, 1921)
            float f0 = 0;
            for (int k = 1888; k < KK; k++) f0 = fmaf(xs[k], xs[k + m], f0);
            dacc += (double)f0;
        }
        cd[m] = dacc;
        __syncthreads();

        // Hankel diagonal recurrence: fp32 16-step segments, fp64 carry
        int dg = tid;
        double gbase = cd[dg];
        Gd[dg] = gbase;
        Gd[dg * LW] = gbase;
        float gf0 = (float)gbase;
        G32[dg] = gf0;
        G32[dg * APG] = gf0;
        float seg = 0.f;
        for (int l = 1; l < LW - dg; l++) {
            int mm = l + dg;
            float delta = fmaf(xs[KK + l - 1], xs[KK + mm - 1],
                               -xs[l - 1] * xs[mm - 1]);
            seg += delta;
            double gv = gbase + (double)seg;
            Gd[l * LW + mm] = gv;
            Gd[mm * LW + l] = gv;
            float gf = (float)gv;
            G32[l * APG + mm] = gf;
            G32[mm * APG + l] = gf;
            if ((l & 15) == 15) { gbase += (double)seg; seg = 0.f; }
        }
        __syncthreads();
    }

    // ========== Lanczos: 3-term + unnormalized carry + every-2nd CGS =======
    {
        float q0 = 1.0f + 0.5f * __sinf(0.7f * (float)tid + 0.3f);
        float n2 = bsum128(q0 * q0, rA);
        Qt[0 * APQT + tid] = q0 * rsqrtf(n2);
        __syncthreads();
    }

    float prevbeta = 0.f;
    bool rownorm = true;   // is Qt[j] normalized on entry?
    for (int j = 0; j < MK; j++) {
        // w = G * Qt[j]  (row may be unnormalized)
        const float4* gr4 = (const float4*)&G32[tid * APG];
        const float4* qr4 = (const float4*)&Qt[j * APQT];
        float4 a4 = make_float4(0.f, 0.f, 0.f, 0.f);
#pragma unroll 8
        for (int l = 0; l < 32; l++) {
            float4 g = gr4[l];
            float4 q = qr4[l];
            a4.x = fmaf(g.x, q.x, a4.x);
            a4.y = fmaf(g.y, q.y, a4.y);
            a4.z = fmaf(g.z, q.z, a4.z);
            a4.w = fmaf(g.w, q.w, a4.w);
        }
        float w = (a4.x + a4.y) + (a4.z + a4.w);
        float myq = Qt[j * APQT + tid];

        float alpha;
        if (rownorm) {
            alpha = bsum128(myq * w, rA);
            if (tid == 0) salpha[j] = (double)alpha;
        } else {
            // joint: dot = un.G.un, s2 = ||un||^2 ; beta_{j-1}=sqrt(s2)
            float2 r = bsum128x2(myq * w, myq * myq, rA);
            float s2 = fmaxf(r.y, 1e-30f);
            float bn = sqrtf(s2);
            float inv = rsqrtf(s2);
            alpha = r.x / s2;
            if (tid == 0) { sbeta[j - 1] = (double)bn; salpha[j] = (double)alpha; }
            myq *= inv;
            Qt[j * APQT + tid] = myq;   // normalize in place (barrier-covered)
            w *= inv;
            prevbeta = bn;
        }
        if (j == MK - 1) break;

        float un = w - alpha * myq;
        if (j > 0) un -= prevbeta * Qt[(j - 1) * APQT + tid];

        bool reorth = ((j & 1) == 1) || (j >= MK - 4);
        if (reorth) {
            int npass = (j >= MK - 8) ? 2 : 1;
            u[tid] = un;
            __syncthreads();
            // pass 0
            {
                const float4* u4 = (const float4*)u;
                float4 uu = u4[lane];
                for (int t = wid; t <= j; t += 4) {
                    const float4* qt4 = (const float4*)&Qt[t * APQT];
                    float4 q = qt4[lane];
                    float s = q.x * uu.x + q.y * uu.y + q.z * uu.z + q.w * uu.w;
#pragma unroll
                    for (int o = 16; o; o >>= 1) s += __shfl_xor_sync(0xffffffffu, s, o);
                    if (lane == 0) cvec[t] = s;
                }
                __syncthreads();
                float corr = 0;
                for (int t = 0; t <= j; t++)
                    corr = fmaf(Qt[t * APQT + tid], cvec[t], corr);
                un = u[tid] - corr;   // keep in register (u[] unchanged)
            }
            if (npass == 2) {
                __syncthreads();     // cover cvec reuse + u rewrite
                u[tid] = un;
                __syncthreads();
                const float4* u4 = (const float4*)u;
                float4 uu = u4[lane];
                for (int t = wid; t <= j; t += 4) {
                    const float4* qt4 = (const float4*)&Qt[t * APQT];
                    float4 q = qt4[lane];
                    float s = q.x * uu.x + q.y * uu.y + q.z * uu.z + q.w * uu.w;
#pragma unroll
                    for (int o = 16; o; o >>= 1) s += __shfl_xor_sync(0xffffffffu, s, o);
                    if (lane == 0) cvec[t] = s;
                }
                __syncthreads();
                float corr = 0;
                for (int t = 0; t <= j; t++)
                    corr = fmaf(Qt[t * APQT + tid], cvec[t], corr);
                un = u[tid] - corr;
            }
            float b2 = bsum128(un * un, rB);
            float bn = sqrtf(fmaxf(b2, 1e-30f));
            if (tid == 0) sbeta[j] = (double)bn;
            Qt[(j + 1) * APQT + tid] = un / bn;
            prevbeta = bn;
            rownorm = true;
        } else {
            Qt[(j + 1) * APQT + tid] = un;   // unnormalized carry
            rownorm = false;
        }
        __syncthreads();
    }
    __syncthreads();

    if (tid < MK) {
        sa32[tid] = (float)salpha[tid];
        float b = (tid < MK - 1) ? (float)sbeta[tid] : 0.f;
        sbf[tid] = b;
        sb232[tid] = b * b;
    }
    __syncthreads();

    // ============ parallel fp32 bisection (8 thr/eig, 9-way, 6 rounds) =====
    {
        int g = tid >> 3, sub = tid & 7;
        int p = MK - 1 - g;
        float lo = 3e38f, hi = -3e38f, bmax = 0.f;
        for (int i = 0; i < MK; i++) {
            float bl = (i > 0) ? sbf[i - 1] : 0.f;
            float br = (i < MK - 1) ? sbf[i] : 0.f;
            float r = fabsf(bl) + fabsf(br);
            lo = fminf(lo, sa32[i] - r);
            hi = fmaxf(hi, sa32[i] + r);
            bmax = fmaxf(bmax, fmaxf(fabsf(sa32[i]), fabsf(br)));
        }
        float gguard = bmax * 1e-6f + 1e-30f;

        for (int round = 0; round < 6; round++) {
            float w = hi - lo;
            float mid = lo + w * (float)(sub + 1) * (1.0f / 9.0f);
            int cnt = 0;
            float d = 1.0f;
            for (int i = 0; i < MK; i++) {
                float off = (i > 0) ? __fdividef(sb232[i - 1], d) : 0.f;
                d = sa32[i] - mid - off;
                cnt += (d < 0.f);
                if (fabsf(d) < gguard) d = -gguard;
            }
            float clo = (cnt <= p) ? mid : lo;
            float chi = (cnt > p) ? mid : hi;
#pragma unroll
            for (int o = 4; o; o >>= 1) {
                clo = fmaxf(clo, __shfl_xor_sync(0xffffffffu, clo, o));
                chi = fminf(chi, __shfl_xor_sync(0xffffffffu, chi, o));
            }
            lo = clo;
            hi = chi;
        }
        if (sub == 0 && g < NR) lam32[g] = 0.5f * (lo + hi);
    }
    __syncthreads();

    // ============ fp32 inverse iteration: TWO guarded-Thomas solves ========
    if (tid < NR) {
        float bmaxf = 0.f;
        for (int i = 0; i < MK; i++)
            bmaxf = fmaxf(bmaxf, fmaxf(fabsf(sa32[i]), fabsf(sbf[i])));
        float guard = bmaxf * 1e-7f + 1e-30f;
        float lv = lam32[tid];
        float* y = Ytr32[tid];
        float* cp = cpw32[tid];
        for (int i = 0; i < MK; i++)
            y[i] = __sinf(0.613f * (float)((i + 2) * (tid + 5)) + 0.21f);
        for (int solve = 0; solve < 2; solve++) {
            float d = sa32[0] - lv;
            if (fabsf(d) < guard) d = (d >= 0.f) ? guard : -guard;
            cp[0] = __fdividef(sbf[0], d);
            y[0] = __fdividef(y[0], d);
            for (int i = 1; i < MK; i++) {
                float mdiag = sa32[i] - lv - sbf[i - 1] * cp[i - 1];
                if (fabsf(mdiag) < guard) mdiag = (mdiag >= 0.f) ? guard : -guard;
                float im = __fdividef(1.f, mdiag);
                if (i < MK - 1) cp[i] = sbf[i] * im;
                y[i] = (y[i] - sbf[i - 1] * y[i - 1]) * im;
            }
            for (int i = MK - 2; i >= 0; i--) y[i] -= cp[i] * y[i + 1];
            float nn = 0.f;
            for (int i = 0; i < MK; i++) nn += y[i] * y[i];
            float inv = rsqrtf(fmaxf(nn, 1e-30f));
            for (int i = 0; i < MK; i++) y[i] *= inv;
        }
    }
    __syncthreads();

    // ================= lift U16 = Q-lift (fp32 accumulate) =================
    {
        float acc[NR];
#pragma unroll
        for (int t = 0; t < NR; t++) acc[t] = 0.f;
        for (int k = 0; k < MK; k++) {
            float q = Qt[k * APQT + tid];
#pragma unroll
            for (int t = 0; t < NR; t++)
                acc[t] = fmaf(q, Ytr32[t][k], acc[t]);
        }
#pragma unroll
        for (int t = 0; t < NR; t++) U16[tid * APR + t] = (double)acc[t];
    }
    __syncthreads();

    // ============ fused-batch fp64 MGS (sliced reductions) ============
#pragma unroll
    for (int a = 0; a < NR; a++) {
        double va = U16[tid * APR + a];
        double dv[NR];
#pragma unroll
        for (int b = a; b < NR; b++) dv[b - a] = va * U16[tid * APR + b];
#pragma unroll
        for (int o = 16; o; o >>= 1)
#pragma unroll
            for (int b = 0; b < NR - a; b++)
                dv[b] += __shfl_xor_sync(0xffffffffu, dv[b], o);
        if (lane == 0)
#pragma unroll
            for (int b = 0; b < NR - a; b++) dred[wid][b] = dv[b];
        __syncthreads();
        double nn = dred[0][0] + dred[1][0] + dred[2][0] + dred[3][0];
        double innn = 1.0 / fmax(nn, 1e-300);
        double inv = sqrt(innn);
#pragma unroll
        for (int b = a + 1; b < NR; b++) {
            double tot = dred[0][b - a] + dred[1][b - a]
                       + dred[2][b - a] + dred[3][b - a];
            U16[tid * APR + b] -= (tot * innn) * va;
        }
        U16[tid * APR + a] = va * inv;
        __syncthreads();
    }

    // ================= W16 = G(fp64) * U16 =================
    {
        double acc[NR];
#pragma unroll
        for (int t = 0; t < NR; t++) acc[t] = 0.0;
        const double* gr = Gd + (size_t)tid * LW;
        for (int l = 0; l < LW; l++) {
            double g = gr[l];
            const double* ur = &U16[l * APR];
#pragma unroll
            for (int t = 0; t < NR; t++) acc[t] += g * ur[t];
        }
#pragma unroll
        for (int t = 0; t < NR; t++) W16[tid * APR + t] = acc[t];
    }
    __syncthreads();

    // ================= H16 = U16^T W16, symmetrized =================
    for (int e = tid; e < NR * NR; e += 128) {
        int a = e / NR, b = e % NR;
        if (a <= b) {
            double s0 = 0, s1 = 0;
            for (int i = 0; i < LW; i += 2) {
                s0 += U16[i * APR + a] * W16[i * APR + b];
                s1 += U16[(i + 1) * APR + a] * W16[(i + 1) * APR + b];
            }
            double s = s0 + s1;
            H16[a * APR + b] = s;
            H16[b * APR + a] = s;
        }
    }
    for (int i = tid; i < NR * NR; i += 128) {
        int a = i / NR, b = i % NR;
        Z16[a * APR + b] = (a == b) ? 1.0 : 0.0;
    }
    __syncthreads();

    // ================= 12x12 fp64 Jacobi, 1 sweep =================
    {
        for (int r = 0; r < NR - 1; r++) {
            if (tid < 6) {
                int p, q;
                if (tid == 0) { p = NR - 1; q = r; }
                else { p = (r + tid) % (NR - 1); q = (r + NR - 1 - tid) % (NR - 1); }
                double app = H16[p * APR + p], aqq = H16[q * APR + q], apq = H16[p * APR + q];
                double c = 1.0, s = 0.0;
                if (fabs(apq) > 0.0) {
                    double th = (aqq - app) / (2.0 * apq);
                    double t = ((th >= 0.0) ? 1.0 : -1.0) /
                               (fabs(th) + sqrt(1.0 + th * th));
                    c = 1.0 / sqrt(1.0 + t * t);
                    s = t * c;
                }
                sp[tid] = p; sq[tid] = q; dc6[tid] = c; ds6[tid] = s;
            }
            __syncthreads();
            if (tid < 6 * NR) {
                int pr = tid / NR, jj = tid % NR;
                int p = sp[pr], q = sq[pr];
                double c = dc6[pr], s = ds6[pr];
                double ap = H16[p * APR + jj], aq = H16[q * APR + jj];
                H16[p * APR + jj] = c * ap - s * aq;
                H16[q * APR + jj] = s * ap + c * aq;
            }
            __syncthreads();
            if (tid < 6 * NR) {
                int pr = tid / NR, rr = tid % NR;
                int p = sp[pr], q = sq[pr];
                double c = dc6[pr], s = ds6[pr];
                double ap = H16[rr * APR + p], aq = H16[rr * APR + q];
                H16[rr * APR + p] = c * ap - s * aq;
                H16[rr * APR + q] = s * ap + c * aq;
                double zp = Z16[rr * APR + p], zq = Z16[rr * APR + q];
                Z16[rr * APR + p] = c * zp - s * zq;
                Z16[rr * APR + q] = s * zp + c * zq;
            }
            __syncthreads();
        }
    }

    // ================= top-4, project back =================
    if (tid == 0) {
        double ev[NR];
        for (int a = 0; a < NR; a++) ev[a] = H16[a * APR + a];
        for (int j = 0; j < 4; j++) {
            int bi = 0;
            double bv = -1e300;
            for (int a = 0; a < NR; a++)
                if (ev[a] > bv) { bv = ev[a]; bi = a; }
            idx4[j] = bi;
            ev[bi] = -1e300;
        }
    }
    __syncthreads();
    {
        float vout[4];
#pragma unroll
        for (int j = 0; j < 4; j++) {
            double s = 0;
#pragma unroll
            for (int a = 0; a < NR; a++)
                s += U16[tid * APR + a] * Z16[a * APR + idx4[j]];
            vout[j] = (float)s;
        }
        *(float4*)&g_V4[(bc * LW + tid) * DCOMP] =
            make_float4(vout[0], vout[1], vout[2], vout[3]);
    }
}

// ---------------------------------------------------------------------------
// Recon: w = T v (4-wide sliding window), conv(w, v) with zero-padded w.
// ---------------------------------------------------------------------------
__global__ void __launch_bounds__(256) recon_kernel(const float* __restrict__ x,
                                                    float* __restrict__ out) {
    __shared__ float xs[NLEN + 8];
    __shared__ float vv[LW];
    __shared__ float wp[127 + KK + 127];   // 2175; interior written by stage 1
    int bc = blockIdx.x;
    int comp = blockIdx.y;
    int tid = threadIdx.x;

    const float* xp = x + bc * NLEN;
    for (int i = tid; i < NLEN; i += 256) xs[i] = xp[i];
    if (tid < 8) xs[NLEN + tid] = 0.f;
    if (tid < LW) vv[tid] = g_V4[(bc * LW + tid) * DCOMP + comp];
    // zero ONLY the pads: [0,127) and [127+KK, 127+KK+127)
    if (tid < 127) {
        wp[tid] = 0.f;
        wp[127 + KK + tid] = 0.f;
    }
    // stage-1 4-wide groups end at 127+1923 (one past KK+1); zero the slack
    if (tid == 127) { wp[127 + KK] = 0.f; wp[127 + KK + 1] = 0.f; wp[127 + KK + 2] = 0.f; }
    __syncthreads();

    // stage 1: w[k] = sum_l xs[k+l] vv[l], 4 outputs per thread-group
    for (int grp = tid; grp <= 480; grp += 256) {
        int k0 = grp * 4;
        float w0 = xs[k0], w1 = xs[k0 + 1], w2 = xs[k0 + 2];
        float a0 = 0, a1 = 0, a2 = 0, a3 = 0;
#pragma unroll 4
        for (int l = 0; l < LW; l++) {
            float w3 = xs[k0 + l + 3];
            float v = vv[l];
            a0 = fmaf(w0, v, a0);
            a1 = fmaf(w1, v, a1);
            a2 = fmaf(w2, v, a2);
            a3 = fmaf(w3, v, a3);
            w0 = w1; w1 = w2; w2 = w3;
        }
        wp[127 + k0] = a0;
        if (k0 + 3 < KK) {
            wp[128 + k0] = a1;
            wp[129 + k0] = a2;
            wp[130 + k0] = a3;
        }
    }
    __syncthreads();

    // stage 2: out[n] = (sum_l vv[l] wp[127+n-l]) / cnt
    float* op = out + ((size_t)comp * NCH + bc) * NLEN;
    for (int grp = tid; grp < 512; grp += 256) {
        int n0 = grp * 4;
        float r1 = wp[128 + n0], r2 = wp[129 + n0], r3 = wp[130 + n0];
        float a0 = 0, a1 = 0, a2 = 0, a3 = 0;
#pragma unroll 4
        for (int l = 0; l < LW; l++) {
            float r0 = wp[127 + n0 - l];
            float v = vv[l];
            a0 = fmaf(v, r0, a0);
            a1 = fmaf(v, r1, a1);
            a2 = fmaf(v, r2, a2);
            a3 = fmaf(v, r3, a3);
            r3 = r2; r2 = r1; r1 = r0;
        }
#pragma unroll
        for (int j = 0; j < 4; j++) {
            int n = n0 + j;
            int cnt = min(min(n + 1, NLEN - n), LW);
            float a = (j == 0) ? a0 : (j == 1) ? a1 : (j == 2) ? a2 : a3;
            op[n] = a / (float)cnt;
        }
    }
}

// ---------------------------------------------------------------------------
extern "C" void kernel_launch(void* const* d_in, const int* in_sizes, int n_in,
                              void* d_out, int out_size) {
    const float* x = (const float*)d_in[0];
    float* out = (float*)d_out;

    const int SMEME = (LW * APG + MK * APQT) * (int)sizeof(float)
                      + 2 * LW * APR * (int)sizeof(double);  // 121664 B
    cudaFuncSetAttribute(eigen_kernel, cudaFuncAttributeMaxDynamicSharedMemorySize, SMEME);

    eigen_kernel<<<NCH, 128, SMEME>>>(x);
    recon_kernel<<<dim3(NCH, DCOMP), 256>>>(x, out);
}

// round 17
// speedup vs baseline: 1.0557x; 1.0557x over previous
#include <cuda_runtime.h>
#include <math.h>

#define NCH   64
#define NLEN  2048
#define LW    128
#define KK    1921
#define DCOMP 4

#define MK    52     // Krylov dimension
#define APG   132    // fp32 G smem pitch (16B-aligned rows, conflict-free f4)
#define APQT  132    // transposed Q pitch
#define NR    12     // refined subspace size
#define APR   13     // U16/W16 pitch (doubles)

__device__ double g_G[NCH * LW * LW];       // fp64 Gram matrices
__device__ float  g_V4[NCH * LW * DCOMP];   // top-4 eigenvectors, interleaved

// single-barrier 128-thread reduction (caller alternates buffers)
__device__ __forceinline__ float bsum128(float v, volatile float* r4) {
#pragma unroll
    for (int o = 16; o; o >>= 1) v += __shfl_xor_sync(0xffffffffu, v, o);
    if ((threadIdx.x & 31) == 0) r4[threadIdx.x >> 5] = v;
    __syncthreads();
    return (r4[0] + r4[1]) + (r4[2] + r4[3]);
}
// joint dual reduction, single barrier
__device__ __forceinline__ float2 bsum128x2(float a, float b, volatile float* r8) {
#pragma unroll
    for (int o = 16; o; o >>= 1) {
        a += __shfl_xor_sync(0xffffffffu, a, o);
        b += __shfl_xor_sync(0xffffffffu, b, o);
    }
    if ((threadIdx.x & 31) == 0) {
        r8[threadIdx.x >> 5] = a;
        r8[4 + (threadIdx.x >> 5)] = b;
    }
    __syncthreads();
    return make_float2((r8[0] + r8[1]) + (r8[2] + r8[3]),
                       (r8[4] + r8[5]) + (r8[6] + r8[7]));
}

// ---------------------------------------------------------------------------
// Fused per-channel solver. 128 threads per CTA, one CTA per channel.
// (exact round-15-measured version)
// ---------------------------------------------------------------------------
__global__ void __launch_bounds__(128, 1) eigen_kernel(const float* __restrict__ x) {
    extern __shared__ char smraw[];
    float*  G32 = (float*)smraw;                 // 128*132 f32
    float*  Qt  = G32 + LW * APG;                // 52*132  f32 (row j = q_j)
    double* U16 = (double*)(Qt + MK * APQT);     // 128*13  f64
    double* W16 = U16 + LW * APR;                // 128*13  f64
    float*  xs  = (float*)W16;                   // overlay (gram stage only)

    __shared__ double cd[LW];
    __shared__ __align__(16) float u[LW];
    __shared__ float  cvec[MK];
    __shared__ float  rA[8], rB[4];
    __shared__ double dred[4][NR];
    __shared__ double salpha[MK];
    __shared__ double sbeta[MK];
    __shared__ float  sa32[MK];
    __shared__ float  sbf[MK];
    __shared__ float  sb232[MK];
    __shared__ float  Ytr32[NR][MK];
    __shared__ float  cpw32[NR][MK];
    __shared__ float  lam32[NR];
    __shared__ double H16[NR * APR];
    __shared__ double Z16[NR * APR];
    __shared__ int    sp[6], sq[6];
    __shared__ double dc6[6], ds6[6];
    __shared__ int    idx4[4];

    int tid = threadIdx.x;
    int lane = tid & 31, wid = tid >> 5;
    int bc = blockIdx.x;
    double* Gd = g_G + (size_t)bc * LW * LW;

    // ================= Gram stage =================
    {
        const float* xp = x + bc * NLEN;
        for (int i = tid; i < NLEN; i += 128) xs[i] = xp[i];
        __syncthreads();

        int m = tid;
        double dacc = 0.0;
        for (int chunk = 0; chunk < 1888; chunk += 32) {
            float f0 = 0, f1 = 0, f2 = 0, f3 = 0;
#pragma unroll
            for (int k = 0; k < 32; k += 4) {
                float4 xk = *(const float4*)&xs[chunk + k];
                f0 = fmaf(xk.x, xs[chunk + k + m],     f0);
                f1 = fmaf(xk.y, xs[chunk + k + 1 + m], f1);
                f2 = fmaf(xk.z, xs[chunk + k + 2 + m], f2);
                f3 = fmaf(xk.w, xs[chunk + k + 3 + m], f3);
            }
            dacc += (double)((f0 + f1) + (f2 + f3));
        }
        {   // tail chunk [1888, 1921)
            float f0 = 0;
            for (int k = 1888; k < KK; k++) f0 = fmaf(xs[k], xs[k + m], f0);
            dacc += (double)f0;
        }
        cd[m] = dacc;
        __syncthreads();

        int dg = tid;
        double gbase = cd[dg];
        Gd[dg] = gbase;
        Gd[dg * LW] = gbase;
        float gf0 = (float)gbase;
        G32[dg] = gf0;
        G32[dg * APG] = gf0;
        float seg = 0.f;
        for (int l = 1; l < LW - dg; l++) {
            int mm = l + dg;
            float delta = fmaf(xs[KK + l - 1], xs[KK + mm - 1],
                               -xs[l - 1] * xs[mm - 1]);
            seg += delta;
            double gv = gbase + (double)seg;
            Gd[l * LW + mm] = gv;
            Gd[mm * LW + l] = gv;
            float gf = (float)gv;
            G32[l * APG + mm] = gf;
            G32[mm * APG + l] = gf;
            if ((l & 15) == 15) { gbase += (double)seg; seg = 0.f; }
        }
        __syncthreads();
    }

    // ========== Lanczos: 3-term + unnormalized carry + every-2nd CGS =======
    {
        float q0 = 1.0f + 0.5f * __sinf(0.7f * (float)tid + 0.3f);
        float n2 = bsum128(q0 * q0, rA);
        Qt[0 * APQT + tid] = q0 * rsqrtf(n2);
        __syncthreads();
    }

    float prevbeta = 0.f;
    bool rownorm = true;
    for (int j = 0; j < MK; j++) {
        const float4* gr4 = (const float4*)&G32[tid * APG];
        const float4* qr4 = (const float4*)&Qt[j * APQT];
        float4 a4 = make_float4(0.f, 0.f, 0.f, 0.f);
#pragma unroll 8
        for (int l = 0; l < 32; l++) {
            float4 g = gr4[l];
            float4 q = qr4[l];
            a4.x = fmaf(g.x, q.x, a4.x);
            a4.y = fmaf(g.y, q.y, a4.y);
            a4.z = fmaf(g.z, q.z, a4.z);
            a4.w = fmaf(g.w, q.w, a4.w);
        }
        float w = (a4.x + a4.y) + (a4.z + a4.w);
        float myq = Qt[j * APQT + tid];

        float alpha;
        if (rownorm) {
            alpha = bsum128(myq * w, rA);
            if (tid == 0) salpha[j] = (double)alpha;
        } else {
            float2 r = bsum128x2(myq * w, myq * myq, rA);
            float s2 = fmaxf(r.y, 1e-30f);
            float bn = sqrtf(s2);
            float inv = rsqrtf(s2);
            alpha = r.x / s2;
            if (tid == 0) { sbeta[j - 1] = (double)bn; salpha[j] = (double)alpha; }
            myq *= inv;
            Qt[j * APQT + tid] = myq;
            w *= inv;
            prevbeta = bn;
        }
        if (j == MK - 1) break;

        float un = w - alpha * myq;
        if (j > 0) un -= prevbeta * Qt[(j - 1) * APQT + tid];

        bool reorth = ((j & 1) == 1) || (j >= MK - 4);
        if (reorth) {
            int npass = (j >= MK - 8) ? 2 : 1;
            u[tid] = un;
            __syncthreads();
            for (int pass = 0; pass < npass; pass++) {
                const float4* u4 = (const float4*)u;
                float4 uu = u4[lane];
                for (int t = wid; t <= j; t += 4) {
                    const float4* qt4 = (const float4*)&Qt[t * APQT];
                    float4 q = qt4[lane];
                    float s = q.x * uu.x + q.y * uu.y + q.z * uu.z + q.w * uu.w;
#pragma unroll
                    for (int o = 16; o; o >>= 1) s += __shfl_xor_sync(0xffffffffu, s, o);
                    if (lane == 0) cvec[t] = s;
                }
                __syncthreads();
                float corr = 0;
                for (int t = 0; t <= j; t++)
                    corr = fmaf(Qt[t * APQT + tid], cvec[t], corr);
                u[tid] -= corr;
                __syncthreads();
            }
            un = u[tid];
            float b2 = bsum128(un * un, rB);
            float bn = sqrtf(fmaxf(b2, 1e-30f));
            if (tid == 0) sbeta[j] = (double)bn;
            Qt[(j + 1) * APQT + tid] = un / bn;
            prevbeta = bn;
            rownorm = true;
        } else {
            Qt[(j + 1) * APQT + tid] = un;
            rownorm = false;
        }
        __syncthreads();
    }
    __syncthreads();

    if (tid < MK) {
        sa32[tid] = (float)salpha[tid];
        float b = (tid < MK - 1) ? (float)sbeta[tid] : 0.f;
        sbf[tid] = b;
        sb232[tid] = b * b;
    }
    __syncthreads();

    // ============ parallel fp32 bisection (8 thr/eig, 9-way, 8 rounds) =====
    {
        int g = tid >> 3, sub = tid & 7;
        int p = MK - 1 - g;
        float lo = 3e38f, hi = -3e38f, bmax = 0.f;
        for (int i = 0; i < MK; i++) {
            float bl = (i > 0) ? sbf[i - 1] : 0.f;
            float br = (i < MK - 1) ? sbf[i] : 0.f;
            float r = fabsf(bl) + fabsf(br);
            lo = fminf(lo, sa32[i] - r);
            hi = fmaxf(hi, sa32[i] + r);
            bmax = fmaxf(bmax, fmaxf(fabsf(sa32[i]), fabsf(br)));
        }
        float gguard = bmax * 1e-6f + 1e-30f;

        for (int round = 0; round < 8; round++) {
            float w = hi - lo;
            float mid = lo + w * (float)(sub + 1) * (1.0f / 9.0f);
            int cnt = 0;
            float d = 1.0f;
            for (int i = 0; i < MK; i++) {
                float off = (i > 0) ? __fdividef(sb232[i - 1], d) : 0.f;
                d = sa32[i] - mid - off;
                cnt += (d < 0.f);
                if (fabsf(d) < gguard) d = -gguard;
            }
            float clo = (cnt <= p) ? mid : lo;
            float chi = (cnt > p) ? mid : hi;
#pragma unroll
            for (int o = 4; o; o >>= 1) {
                clo = fmaxf(clo, __shfl_xor_sync(0xffffffffu, clo, o));
                chi = fminf(chi, __shfl_xor_sync(0xffffffffu, chi, o));
            }
            lo = clo;
            hi = chi;
        }
        if (sub == 0 && g < NR) lam32[g] = 0.5f * (lo + hi);
    }
    __syncthreads();

    // ============ fp32 inverse iteration: single guarded-Thomas solve ======
    if (tid < NR) {
        float bmaxf = 0.f;
        for (int i = 0; i < MK; i++)
            bmaxf = fmaxf(bmaxf, fmaxf(fabsf(sa32[i]), fabsf(sbf[i])));
        float guard = bmaxf * 1e-7f + 1e-30f;
        float lv = lam32[tid];
        float* y = Ytr32[tid];
        float* cp = cpw32[tid];
        for (int i = 0; i < MK; i++)
            y[i] = __sinf(0.613f * (float)((i + 2) * (tid + 5)) + 0.21f);
        {
            float d = sa32[0] - lv;
            if (fabsf(d) < guard) d = (d >= 0.f) ? guard : -guard;
            cp[0] = __fdividef(sbf[0], d);
            y[0] = __fdividef(y[0], d);
            for (int i = 1; i < MK; i++) {
                float mdiag = sa32[i] - lv - sbf[i - 1] * cp[i - 1];
                if (fabsf(mdiag) < guard) mdiag = (mdiag >= 0.f) ? guard : -guard;
                float im = __fdividef(1.f, mdiag);
                if (i < MK - 1) cp[i] = sbf[i] * im;
                y[i] = (y[i] - sbf[i - 1] * y[i - 1]) * im;
            }
            for (int i = MK - 2; i >= 0; i--) y[i] -= cp[i] * y[i + 1];
            float nn = 0.f;
            for (int i = 0; i < MK; i++) nn += y[i] * y[i];
            float inv = rsqrtf(fmaxf(nn, 1e-30f));
            for (int i = 0; i < MK; i++) y[i] *= inv;
        }
    }
    __syncthreads();

    // ================= lift U16 = Q-lift (fp32 accumulate) =================
    {
        float acc[NR];
#pragma unroll
        for (int t = 0; t < NR; t++) acc[t] = 0.f;
        for (int k = 0; k < MK; k++) {
            float q = Qt[k * APQT + tid];
#pragma unroll
            for (int t = 0; t < NR; t++)
                acc[t] = fmaf(q, Ytr32[t][k], acc[t]);
        }
#pragma unroll
        for (int t = 0; t < NR; t++) U16[tid * APR + t] = (double)acc[t];
    }
    __syncthreads();

    // ============ fused-batch fp64 MGS (sliced reductions) ============
#pragma unroll
    for (int a = 0; a < NR; a++) {
        double va = U16[tid * APR + a];
        double dv[NR];
#pragma unroll
        for (int b = a; b < NR; b++) dv[b - a] = va * U16[tid * APR + b];
#pragma unroll
        for (int o = 16; o; o >>= 1)
#pragma unroll
            for (int b = 0; b < NR - a; b++)
                dv[b] += __shfl_xor_sync(0xffffffffu, dv[b], o);
        if (lane == 0)
#pragma unroll
            for (int b = 0; b < NR - a; b++) dred[wid][b] = dv[b];
        __syncthreads();
        double nn = dred[0][0] + dred[1][0] + dred[2][0] + dred[3][0];
        double innn = 1.0 / fmax(nn, 1e-300);
        double inv = sqrt(innn);
#pragma unroll
        for (int b = a + 1; b < NR; b++) {
            double tot = dred[0][b - a] + dred[1][b - a]
                       + dred[2][b - a] + dred[3][b - a];
            U16[tid * APR + b] -= (tot * innn) * va;
        }
        U16[tid * APR + a] = va * inv;
        __syncthreads();
    }

    // ================= W16 = G(fp64) * U16 =================
    {
        double acc[NR];
#pragma unroll
        for (int t = 0; t < NR; t++) acc[t] = 0.0;
        const double* gr = Gd + (size_t)tid * LW;
        for (int l = 0; l < LW; l++) {
            double g = gr[l];
            const double* ur = &U16[l * APR];
#pragma unroll
            for (int t = 0; t < NR; t++) acc[t] += g * ur[t];
        }
#pragma unroll
        for (int t = 0; t < NR; t++) W16[tid * APR + t] = acc[t];
    }
    __syncthreads();

    // ================= H16 = U16^T W16, symmetrized =================
    for (int e = tid; e < NR * NR; e += 128) {
        int a = e / NR, b = e % NR;
        if (a <= b) {
            double s0 = 0, s1 = 0;
            for (int i = 0; i < LW; i += 2) {
                s0 += U16[i * APR + a] * W16[i * APR + b];
                s1 += U16[(i + 1) * APR + a] * W16[(i + 1) * APR + b];
            }
            double s = s0 + s1;
            H16[a * APR + b] = s;
            H16[b * APR + a] = s;
        }
    }
    for (int i = tid; i < NR * NR; i += 128) {
        int a = i / NR, b = i % NR;
        Z16[a * APR + b] = (a == b) ? 1.0 : 0.0;
    }
    __syncthreads();

    // ================= 12x12 fp64 Jacobi, 1 sweep =================
    {
        for (int r = 0; r < NR - 1; r++) {
            if (tid < 6) {
                int p, q;
                if (tid == 0) { p = NR - 1; q = r; }
                else { p = (r + tid) % (NR - 1); q = (r + NR - 1 - tid) % (NR - 1); }
                double app = H16[p * APR + p], aqq = H16[q * APR + q], apq = H16[p * APR + q];
                double c = 1.0, s = 0.0;
                if (fabs(apq) > 0.0) {
                    double th = (aqq - app) / (2.0 * apq);
                    double t = ((th >= 0.0) ? 1.0 : -1.0) /
                               (fabs(th) + sqrt(1.0 + th * th));
                    c = 1.0 / sqrt(1.0 + t * t);
                    s = t * c;
                }
                sp[tid] = p; sq[tid] = q; dc6[tid] = c; ds6[tid] = s;
            }
            __syncthreads();
            if (tid < 6 * NR) {
                int pr = tid / NR, jj = tid % NR;
                int p = sp[pr], q = sq[pr];
                double c = dc6[pr], s = ds6[pr];
                double ap = H16[p * APR + jj], aq = H16[q * APR + jj];
                H16[p * APR + jj] = c * ap - s * aq;
                H16[q * APR + jj] = s * ap + c * aq;
            }
            __syncthreads();
            if (tid < 6 * NR) {
                int pr = tid / NR, rr = tid % NR;
                int p = sp[pr], q = sq[pr];
                double c = dc6[pr], s = ds6[pr];
                double ap = H16[rr * APR + p], aq = H16[rr * APR + q];
                H16[rr * APR + p] = c * ap - s * aq;
                H16[rr * APR + q] = s * ap + c * aq;
                double zp = Z16[rr * APR + p], zq = Z16[rr * APR + q];
                Z16[rr * APR + p] = c * zp - s * zq;
                Z16[rr * APR + q] = s * zp + c * zq;
            }
            __syncthreads();
        }
    }

    // ================= top-4, project back =================
    if (tid == 0) {
        double ev[NR];
        for (int a = 0; a < NR; a++) ev[a] = H16[a * APR + a];
        for (int j = 0; j < 4; j++) {
            int bi = 0;
            double bv = -1e300;
            for (int a = 0; a < NR; a++)
                if (ev[a] > bv) { bv = ev[a]; bi = a; }
            idx4[j] = bi;
            ev[bi] = -1e300;
        }
    }
    __syncthreads();
    {
        float vout[4];
#pragma unroll
        for (int j = 0; j < 4; j++) {
            double s = 0;
#pragma unroll
            for (int a = 0; a < NR; a++)
                s += U16[tid * APR + a] * Z16[a * APR + idx4[j]];
            vout[j] = (float)s;
        }
        *(float4*)&g_V4[(bc * LW + tid) * DCOMP] =
            make_float4(vout[0], vout[1], vout[2], vout[3]);
    }
}

// ---------------------------------------------------------------------------
// Recon: float4 sliding windows (conflict-free LDS.128, 1 load / 4 taps).
// ---------------------------------------------------------------------------
__global__ void __launch_bounds__(256) recon_kernel(const float* __restrict__ x,
                                                    float* __restrict__ out) {
    __shared__ __align__(16) float xs[NLEN + 8];
    __shared__ float vv[LW];
    __shared__ __align__(16) float wp[127 + KK + 128];   // 2176 (16B multiple)
    int bc = blockIdx.x;
    int comp = blockIdx.y;
    int tid = threadIdx.x;

    const float* xp = x + bc * NLEN;
    for (int i = tid; i < NLEN; i += 256) xs[i] = xp[i];
    if (tid < 8) xs[NLEN + tid] = 0.f;
    if (tid < LW) vv[tid] = g_V4[(bc * LW + tid) * DCOMP + comp];
    for (int i = tid; i < 127 + KK + 128; i += 256) wp[i] = 0.f;
    __syncthreads();

    // stage 1: w[k] = sum_l xs[k+l] vv[l]; float4 window + carry
    for (int grp = tid; grp <= 480; grp += 256) {
        int k0 = grp * 4;
        const float4* xs4 = (const float4*)xs;
        float4 f0v = xs4[k0 >> 2];
        float w0 = f0v.x, w1 = f0v.y, w2 = f0v.z, carry = f0v.w;
        float a0 = 0, a1 = 0, a2 = 0, a3 = 0;
#pragma unroll 4
        for (int l = 0; l < LW; l += 4) {
            float4 nf = xs4[(k0 + l + 4) >> 2];
            // l+0: w3 = carry
            float v = vv[l];
            a0 = fmaf(w0, v, a0); a1 = fmaf(w1, v, a1);
            a2 = fmaf(w2, v, a2); a3 = fmaf(carry, v, a3);
            w0 = w1; w1 = w2; w2 = carry;
            // l+1: w3 = nf.x
            v = vv[l + 1];
            a0 = fmaf(w0, v, a0); a1 = fmaf(w1, v, a1);
            a2 = fmaf(w2, v, a2); a3 = fmaf(nf.x, v, a3);
            w0 = w1; w1 = w2; w2 = nf.x;
            // l+2: w3 = nf.y
            v = vv[l + 2];
            a0 = fmaf(w0, v, a0); a1 = fmaf(w1, v, a1);
            a2 = fmaf(w2, v, a2); a3 = fmaf(nf.y, v, a3);
            w0 = w1; w1 = w2; w2 = nf.y;
            // l+3: w3 = nf.z ; new carry = nf.w
            v = vv[l + 3];
            a0 = fmaf(w0, v, a0); a1 = fmaf(w1, v, a1);
            a2 = fmaf(w2, v, a2); a3 = fmaf(nf.z, v, a3);
            w0 = w1; w1 = w2; w2 = nf.z;
            carry = nf.w;
        }
        wp[127 + k0] = a0;
        if (k0 + 3 < KK) {
            wp[128 + k0] = a1;
            wp[129 + k0] = a2;
            wp[130 + k0] = a3;
        }
    }
    __syncthreads();

    // stage 2: out[n] = (sum_l vv[l] wp[127+n-l]) / cnt; float4 descending
    float* op = out + ((size_t)comp * NCH + bc) * NLEN;
    for (int grp = tid; grp < 512; grp += 256) {
        int n0 = grp * 4;
        const float4* wp4 = (const float4*)wp;
        float r1 = wp[128 + n0], r2 = wp[129 + n0], r3 = wp[130 + n0];
        float a0 = 0, a1 = 0, a2 = 0, a3 = 0;
#pragma unroll 4
        for (int l = 0; l < LW; l += 4) {
            // aligned load of wp[124+n0-l .. 127+n0-l]
            float4 f = wp4[(124 + n0 - l) >> 2];
            // consume in order r0 = f.w, f.z, f.y, f.x
            float v = vv[l];
            float r0 = f.w;
            a0 = fmaf(v, r0, a0); a1 = fmaf(v, r1, a1);
            a2 = fmaf(v, r2, a2); a3 = fmaf(v, r3, a3);
            r3 = r2; r2 = r1; r1 = r0;
            v = vv[l + 1];
            r0 = f.z;
            a0 = fmaf(v, r0, a0); a1 = fmaf(v, r1, a1);
            a2 = fmaf(v, r2, a2); a3 = fmaf(v, r3, a3);
            r3 = r2; r2 = r1; r1 = r0;
            v = vv[l + 2];
            r0 = f.y;
            a0 = fmaf(v, r0, a0); a1 = fmaf(v, r1, a1);
            a2 = fmaf(v, r2, a2); a3 = fmaf(v, r3, a3);
            r3 = r2; r2 = r1; r1 = r0;
            v = vv[l + 3];
            r0 = f.x;
            a0 = fmaf(v, r0, a0); a1 = fmaf(v, r1, a1);
            a2 = fmaf(v, r2, a2); a3 = fmaf(v, r3, a3);
            r3 = r2; r2 = r1; r1 = r0;
        }
#pragma unroll
        for (int j = 0; j < 4; j++) {
            int n = n0 + j;
            int cnt = min(min(n + 1, NLEN - n), LW);
            float a = (j == 0) ? a0 : (j == 1) ? a1 : (j == 2) ? a2 : a3;
            op[n] = a / (float)cnt;
        }
    }
}

// ---------------------------------------------------------------------------
extern "C" void kernel_launch(void* const* d_in, const int* in_sizes, int n_in,
                              void* d_out, int out_size) {
    const float* x = (const float*)d_in[0];
    float* out = (float*)d_out;

    const int SMEME = (LW * APG + MK * APQT) * (int)sizeof(float)
                      + 2 * LW * APR * (int)sizeof(double);  // 121664 B
    cudaFuncSetAttribute(eigen_kernel, cudaFuncAttributeMaxDynamicSharedMemorySize, SMEME);

    eigen_kernel<<<NCH, 128, SMEME>>>(x);
    recon_kernel<<<dim3(NCH, DCOMP), 256>>>(x, out);
}